// round 17
// baseline (speedup 1.0000x reference)
#include <cuda_runtime.h>
#include <cuda_fp16.h>
#include <cstdint>

#define S_ 4096
#define M_ 32
#define D_ 420
#define H_ 840
#define KP_ 424   // padded fp16 K-stride for K=420 rows (848B, 16B-aligned)

// ------------- scratch (static device globals; 256B-aligned for cp.async) --------
__device__ __align__(256) int    g_rowmap[S_ * M_];             // compact row -> s*32+m
__device__ int    g_nact;                                       // number of active rows
__device__ __align__(256) float  g_invN[S_];                    // 1/numInputs[s]
__device__ __align__(256) __half g_Xh[(size_t)S_ * M_ * KP_];   // gathered fp16 inputs
__device__ __align__(256) __half g_H1h[(size_t)S_ * M_ * KP_];  // layer-1 out (fp16)
__device__ __align__(256) float  g_pooled[(size_t)S_ * D_];     // ragged-mean numerator
__device__ __align__(256) __half g_Ph[(size_t)S_ * KP_];        // pooled, fp16 (padded)
__device__ __align__(256) __half g_Yh[(size_t)S_ * H_];         // layer-3 out (fp16)
__device__ __align__(256) __half g_W1h[D_ * KP_];               // fp16 weights [N][KP]
__device__ __align__(256) __half g_W2h[D_ * KP_];
__device__ __align__(256) __half g_W3h[H_ * KP_];
__device__ __align__(256) __half g_W4h[D_ * H_];                // K=840, natural

__device__ __forceinline__ uint32_t packh2(float lo, float hi) {
    uint32_t r;
    asm("cvt.rn.f16x2.f32 %0, %1, %2;" : "=r"(r) : "f"(hi), "f"(lo));
    return r;
}
__device__ __forceinline__ void mma_f16(float& d0, float& d1, float& d2, float& d3,
                                        uint32_t a0, uint32_t a1, uint32_t a2,
                                        uint32_t a3, uint32_t b0, uint32_t b1) {
    asm volatile(
        "mma.sync.aligned.m16n8k16.row.col.f32.f16.f16.f32 "
        "{%0,%1,%2,%3}, {%4,%5,%6,%7}, {%8,%9}, {%0,%1,%2,%3};"
        : "+f"(d0), "+f"(d1), "+f"(d2), "+f"(d3)
        : "r"(a0), "r"(a1), "r"(a2), "r"(a3), "r"(b0), "r"(b1));
}
__device__ __forceinline__ void ldsm4(uint32_t& r0, uint32_t& r1, uint32_t& r2,
                                      uint32_t& r3, uint32_t addr) {
    asm volatile("ldmatrix.sync.aligned.m8n8.x4.shared.b16 {%0,%1,%2,%3}, [%4];"
                 : "=r"(r0), "=r"(r1), "=r"(r2), "=r"(r3) : "r"(addr));
}
__device__ __forceinline__ void ldsm2(uint32_t& r0, uint32_t& r1, uint32_t addr) {
    asm volatile("ldmatrix.sync.aligned.m8n8.x2.shared.b16 {%0,%1}, [%2];"
                 : "=r"(r0), "=r"(r1) : "r"(addr));
}
__device__ __forceinline__ uint32_t smem_u32(const void* p) {
    uint32_t a;
    asm("{ .reg .u64 t; cvta.to.shared.u64 t, %1; cvt.u32.u64 %0, t; }"
        : "=r"(a) : "l"(p));
    return a;
}
__device__ __forceinline__ void cp16(uint32_t dst, const void* src, uint32_t srcsz) {
    asm volatile("cp.async.cg.shared.global [%0], [%1], 16, %2;"
                 :: "r"(dst), "l"(src), "r"(srcsz) : "memory");
}
#define CP_COMMIT() asm volatile("cp.async.commit_group;" ::: "memory")
#define CP_WAIT(n)  asm volatile("cp.async.wait_group %0;" :: "n"(n) : "memory")

// ---------------- setup: prefix-scan numInputs, build compact row map -------------
__global__ void setup_kernel(const int* __restrict__ numInputs) {
    __shared__ int s_warp[8];
    __shared__ int s_woff[8];
    int t = threadIdx.x;
    int base = t * 16;
    int local[16];
    int run = 0;
#pragma unroll
    for (int j = 0; j < 16; j++) { local[j] = run; run += numInputs[base + j]; }
    int lane = t & 31, warp = t >> 5;
    int inc = run;
#pragma unroll
    for (int o = 1; o < 32; o <<= 1) {
        int v = __shfl_up_sync(0xffffffffu, inc, o);
        if (lane >= o) inc += v;
    }
    if (lane == 31) s_warp[warp] = inc;
    __syncthreads();
    if (t == 0) {
        int r = 0;
        for (int w = 0; w < 8; w++) { s_woff[w] = r; r += s_warp[w]; }
        g_nact = r;
    }
    __syncthreads();
    int thrOff = s_woff[warp] + (inc - run);
    for (int j = 0; j < 16; j++) {
        int s = base + j;
        int n = numInputs[s];
        g_invN[s] = 1.0f / (float)n;
        int off = thrOff + local[j];
        for (int m = 0; m < n; m++) g_rowmap[off + m] = s * M_ + m;
    }
}

// granule-vectorized prep: zero g_pooled, weights->fp16 (pad zeroed), H1h K-pad zero
__global__ void prep_kernel(const float* __restrict__ W1, const float* __restrict__ W2,
                            const float* __restrict__ W3, const float* __restrict__ W4) {
    const int NPZ = S_ * D_ / 4;
    const int GW12 = D_ * 53, GW3 = H_ * 53;
    const int GW4 = D_ * (H_ / 8);
    const int NH1P = S_ * M_;
    int i = blockIdx.x * blockDim.x + threadIdx.x;
    if (i < NPZ) {
        ((float4*)g_pooled)[i] = make_float4(0.f, 0.f, 0.f, 0.f);
        return;
    }
    i -= NPZ;
    if (i < 2 * GW12 + GW3) {
        const float* Ws; __half* Wd;
        if (i < GW12) { Ws = W1; Wd = g_W1h; }
        else if (i < 2 * GW12) { Ws = W2; Wd = g_W2h; i -= GW12; }
        else { Ws = W3; Wd = g_W3h; i -= 2 * GW12; }
        int r = i / 53, g = i - r * 53;
        uint4 u;
        if (g == 52) {
            float4 v = *(const float4*)(Ws + (size_t)r * D_ + 416);
            u.x = packh2(v.x, v.y); u.y = packh2(v.z, v.w);
            u.z = 0u; u.w = 0u;
        } else {
            float4 v0 = *(const float4*)(Ws + (size_t)r * D_ + g * 8);
            float4 v1 = *(const float4*)(Ws + (size_t)r * D_ + g * 8 + 4);
            u.x = packh2(v0.x, v0.y); u.y = packh2(v0.z, v0.w);
            u.z = packh2(v1.x, v1.y); u.w = packh2(v1.z, v1.w);
        }
        *(uint4*)(Wd + (size_t)r * KP_ + g * 8) = u;
        return;
    }
    i -= 2 * GW12 + GW3;
    if (i < GW4) {
        float4 v0 = *(const float4*)(W4 + (size_t)i * 8);
        float4 v1 = *(const float4*)(W4 + (size_t)i * 8 + 4);
        uint4 u;
        u.x = packh2(v0.x, v0.y); u.y = packh2(v0.z, v0.w);
        u.z = packh2(v1.x, v1.y); u.w = packh2(v1.z, v1.w);
        *(uint4*)(g_W4h + (size_t)i * 8) = u;
        return;
    }
    i -= GW4;
    if (i < NH1P) {
        *(uint2*)(g_H1h + (size_t)i * KP_ + D_) = make_uint2(0u, 0u);
    }
}

// gather + convert active rows of all_x -> g_Xh fp16, 16B granules (53 per row)
__global__ void convert_x_kernel(const float* __restrict__ all_x) {
    const int total = g_nact * 53;
    int idx = blockIdx.x * blockDim.x + threadIdx.x;
    if (idx >= total) return;
    int r = idx / 53, g = idx - r * 53;
    const float* src = all_x + (size_t)g_rowmap[r] * D_;
    uint4 u;
    if (g == 52) {
        float4 v = *(const float4*)(src + 416);
        u.x = packh2(v.x, v.y); u.y = packh2(v.z, v.w);
        u.z = 0u; u.w = 0u;
    } else {
        float4 v0 = *(const float4*)(src + g * 8);
        float4 v1 = *(const float4*)(src + g * 8 + 4);
        u.x = packh2(v0.x, v0.y); u.y = packh2(v0.z, v0.w);
        u.z = packh2(v1.x, v1.y); u.w = packh2(v1.z, v1.w);
    }
    *(uint4*)(g_Xh + (size_t)r * KP_ + g * 8) = u;
}

// convert g_pooled -> g_Ph fp16 (padded), 16B granules
__global__ void convert_p_kernel() {
    int idx = blockIdx.x * blockDim.x + threadIdx.x;
    if (idx >= S_ * 53) return;
    int r = idx / 53, g = idx - r * 53;
    const float* src = g_pooled + (size_t)r * D_;
    uint4 u;
    if (g == 52) {
        float4 v = *(const float4*)(src + 416);
        u.x = packh2(v.x, v.y); u.y = packh2(v.z, v.w);
        u.z = 0u; u.w = 0u;
    } else {
        float4 v0 = *(const float4*)(src + g * 8);
        float4 v1 = *(const float4*)(src + g * 8 + 4);
        u.x = packh2(v0.x, v0.y); u.y = packh2(v0.z, v0.w);
        u.z = packh2(v1.x, v1.y); u.w = packh2(v1.z, v1.w);
    }
    *(uint4*)(g_Ph + (size_t)r * KP_ + g * 8) = u;
}

// ============= fused A-resident GEMM for layers 1 & 2 (K=420, N=420) ==============
// MODE 1: A = g_Xh -> g_H1h.  MODE 2: A = g_H1h -> pooled (segmented atomics).
// A tile 128 x 424 halfs resident in smem at NATURAL 848B row stride (conflict-free
// ldmatrix: 848*r mod 128 all-distinct). B streamed per (y,kt) via 3-stage pipeline.
// 256 threads, 8 warps 4Mx2N, warp tile 32x56 per y-subtile, frag double-buffering.
template <int MODE>
__global__ void __launch_bounds__(256, 1)
gemm_fused(const float* __restrict__ bias) {
    constexpr int BM = 128, KT = 7, YT = 4;
    constexpr uint32_t ABYTES = BM * 848u;           // 108544
    constexpr uint32_t BSTG = 112 * 144u;            // 16128
    constexpr uint32_t OFF_B = ABYTES;
    constexpr uint32_t OFF_EP = ABYTES + 3 * BSTG;   // 156928
    constexpr int EPSTR = 116;
    constexpr int TOTAL = YT * KT;                   // 28 steps

    extern __shared__ __align__(16) char smemc[];
    const uint32_t sb = smem_u32(smemc);

    const int nrows = g_nact;
    const int row0 = blockIdx.x * BM;
    if (row0 >= nrows) return;

    const __half* ApH = (MODE == 1) ? g_Xh : g_H1h;
    const __half* Wh  = (MODE == 1) ? g_W1h : g_W2h;

    const int t = threadIdx.x, lane = t & 31, wid = t >> 5;
    const int warpM = wid & 3, warpN = wid >> 2;
    const int grp = lane >> 2, qid = lane & 3;
    const int r8 = lane & 7, sub = lane >> 3;

    // ldmatrix lane bases
    const uint32_t aB = (uint32_t)((warpM * 32 + (sub & 1) * 8 + r8) * 848
                                   + (sub >> 1) * 16);
    const uint32_t bBr = (uint32_t)((warpN * 56 + (sub >> 1) * 8 + r8) * 144
                                    + (sub & 1) * 16);
    const uint32_t bB6r = (uint32_t)((warpN * 56 + 48 + r8) * 144 + (sub & 1) * 16);

    // ---- issue full A tile + B(0); then B(1) ----
    {
#pragma unroll
        for (int i = 0; i < 32; i++) {
            int idx = i * 256 + t;
            int m = idx >> 6, g = idx & 63;
            if (g < 53) {
                int grow = row0 + m;
                bool v = grow < nrows;
                uint32_t sz = v ? 16u : 0u;
                cp16(sb + (uint32_t)(m * 848 + g * 16),
                     ApH + (size_t)(v ? grow : 0) * KP_ + g * 8, sz);
            }
        }
    }
    auto issueB = [&](int step) {
        int y = step / KT, kt = step - y * KT;
        const uint32_t sbase = sb + OFF_B + (uint32_t)(step % 3) * BSTG;
        const int kb = kt * 64;
#pragma unroll
        for (int i = 0; i < 4; i++) {
            int idx = i * 256 + t;
            if (idx < 896) {
                int n = idx >> 3, g = idx & 7;
                int gcol = y * 112 + n;
                bool v = gcol < D_;
                uint32_t sz = (v && (kb + g * 8 + 8) <= KP_) ? 16u : 0u;
                cp16(sbase + (uint32_t)(n * 144 + g * 16),
                     Wh + (size_t)(v ? gcol : 0) * KP_ + kb + g * 8, sz);
            }
        }
        CP_COMMIT();
    };
    issueB(0);     // group 0 = A + B(0)
    issueB(1);     // group 1 = B(1)

    // ---- MODE 2: per-CTA segment scan (once; overlaps async loads) ----
    float* ep = (float*)(smemc + OFF_EP);
    int* sample    = (int*)(smemc + OFF_EP + (uint32_t)BM * EPSTR * 4);
    int* segstart  = sample + BM;
    int* segsample = segstart + BM + 1;
    int* pnseg     = segsample + BM;
    if (MODE == 2) {
        if (t < BM) {
            int g = row0 + t;
            sample[t] = (g < nrows) ? (g_rowmap[g] >> 5) : -1;
        }
        __syncthreads();
        if (t == 0) {
            int lim = nrows - row0; if (lim > BM) lim = BM;
            int ns = 0, cur = -2;
            for (int r = 0; r < lim; r++) {
                int s = sample[r];
                if (s != cur) { segstart[ns] = r; segsample[ns] = s; ns++; cur = s; }
            }
            segstart[ns] = lim;
            *pnseg = ns;
        }
    }

    uint32_t afb[2][2][4], bfb[2][7][2];
    auto ldfrag = [&](uint32_t stb, int kt, int s16, uint32_t af[2][4],
                      uint32_t bf[7][2]) {
        const uint32_t ks = (uint32_t)(s16 * 32);
        const uint32_t ka = (uint32_t)(kt * 128) + ks;
        ldsm4(bf[0][0], bf[0][1], bf[1][0], bf[1][1], stb + bBr + ks);
        ldsm4(bf[2][0], bf[2][1], bf[3][0], bf[3][1], stb + bBr + 2304 + ks);
        ldsm4(bf[4][0], bf[4][1], bf[5][0], bf[5][1], stb + bBr + 4608 + ks);
        ldsm2(bf[6][0], bf[6][1], stb + bB6r + ks);
        ldsm4(af[0][0], af[0][1], af[0][2], af[0][3], sb + aB + ka);
        ldsm4(af[1][0], af[1][1], af[1][2], af[1][3], sb + aB + 13568 + ka);
    };

    int step = 0;
    for (int y = 0; y < YT; y++) {
        float acc[2][7][4];
#pragma unroll
        for (int mt = 0; mt < 2; mt++)
#pragma unroll
            for (int nt = 0; nt < 7; nt++)
#pragma unroll
                for (int c = 0; c < 4; c++) acc[mt][nt][c] = 0.0f;

        for (int kt = 0; kt < KT; kt++, step++) {
            if (step == TOTAL - 1) { CP_WAIT(0); } else { CP_WAIT(1); }
            __syncthreads();
            if (step + 2 < TOTAL) issueB(step + 2);

            const uint32_t stb = sb + OFF_B + (uint32_t)(step % 3) * BSTG;
            ldfrag(stb, kt, 0, afb[0], bfb[0]);
#pragma unroll
            for (int s16 = 0; s16 < 4; s16++) {
                const int cur = s16 & 1;
                if (s16 < 3) ldfrag(stb, kt, s16 + 1, afb[cur ^ 1], bfb[cur ^ 1]);
#pragma unroll
                for (int mt = 0; mt < 2; mt++)
#pragma unroll
                    for (int nt = 0; nt < 7; nt++)
                        mma_f16(acc[mt][nt][0], acc[mt][nt][1],
                                acc[mt][nt][2], acc[mt][nt][3],
                                afb[cur][mt][0], afb[cur][mt][1],
                                afb[cur][mt][2], afb[cur][mt][3],
                                bfb[cur][nt][0], bfb[cur][nt][1]);
            }
        }

        // ---- epilogue for this y (cols y*112 .. y*112+111) ----
        if (MODE == 1) {
#pragma unroll
            for (int mt = 0; mt < 2; mt++) {
                int r = row0 + warpM * 32 + mt * 16 + grp;
#pragma unroll
                for (int nt = 0; nt < 7; nt++) {
                    int gcol = y * 112 + warpN * 56 + nt * 8 + 2 * qid;
                    if (gcol >= D_) continue;
                    float b0 = bias[gcol];
                    float b1 = bias[gcol + 1];
                    if (r < nrows)
                        *(uint32_t*)(g_H1h + (size_t)r * KP_ + gcol) =
                            packh2(fmaxf(acc[0][nt][0 + 0] * 0.f + acc[mt][nt][0] + b0, 0.0f) * 1.0f,
                                   fmaxf(acc[mt][nt][1] + b1, 0.0f));
                    if (r + 8 < nrows)
                        *(uint32_t*)(g_H1h + (size_t)(r + 8) * KP_ + gcol) =
                            packh2(fmaxf(acc[mt][nt][2] + b0, 0.0f),
                                   fmaxf(acc[mt][nt][3] + b1, 0.0f));
                }
            }
        } else {
#pragma unroll
            for (int mt = 0; mt < 2; mt++) {
                int r = warpM * 32 + mt * 16 + grp;
#pragma unroll
                for (int nt = 0; nt < 7; nt++) {
                    int c = warpN * 56 + nt * 8 + 2 * qid;
                    int gcol = y * 112 + c;
                    float b0 = (gcol < D_) ? bias[gcol] : 0.0f;
                    float b1 = (gcol + 1 < D_) ? bias[gcol + 1] : 0.0f;
                    *(float2*)(ep + r * EPSTR + c) =
                        make_float2(fmaxf(acc[mt][nt][0] + b0, 0.0f),
                                    fmaxf(acc[mt][nt][1] + b1, 0.0f));
                    *(float2*)(ep + (r + 8) * EPSTR + c) =
                        make_float2(fmaxf(acc[mt][nt][2] + b0, 0.0f),
                                    fmaxf(acc[mt][nt][3] + b1, 0.0f));
                }
            }
            __syncthreads();
            if (t < 224) {
                int c = (t < 112) ? t : t - 112;
                int sset = (t < 112) ? 0 : 1;
                int gcol = y * 112 + c;
                if (gcol < D_) {
                    int ns = *pnseg;
                    for (int seg = sset; seg < ns; seg += 2) {
                        int r = segstart[seg], e = segstart[seg + 1];
                        float s0 = 0.f, s1 = 0.f, s2 = 0.f, s3 = 0.f;
                        for (; r + 3 < e; r += 4) {
                            s0 += ep[(r + 0) * EPSTR + c];
                            s1 += ep[(r + 1) * EPSTR + c];
                            s2 += ep[(r + 2) * EPSTR + c];
                            s3 += ep[(r + 3) * EPSTR + c];
                        }
                        for (; r < e; r++) s0 += ep[r * EPSTR + c];
                        atomicAdd(&g_pooled[(size_t)segsample[seg] * D_ + gcol],
                                  (s0 + s1) + (s2 + s3));
                    }
                }
            }
            __syncthreads();
        }
    }
}

// ---------------- streaming fp16 mma GEMM (layers 3 & 4), from R16 ----------------
// MODE 3: A = g_Ph (1/n in epilogue) -> g_Yh, rows = S
// MODE 4: A = g_Yh -> d_out fp32, rows = S
template <int MODE, int K>
__global__ void __launch_bounds__(256, 2)
gemm_h(const float* __restrict__ bias, float* __restrict__ OutExt) {
    constexpr int BM = 128, BK = 64;
    constexpr int KT = (K + BK - 1) / BK;
    constexpr int NW  = (MODE == 3) ? H_ : D_;
    constexpr int ASTH = (MODE == 4) ? H_ : KP_;
    constexpr int WST  = (MODE == 4) ? H_ : KP_;
    constexpr int KLIM = (MODE == 4) ? H_ : KP_;
    constexpr int ATILEB = BM * 144;
    constexpr int BTILEB = 112 * 144;
    constexpr int STAGEB = ATILEB + BTILEB;

    extern __shared__ __align__(16) char smemc[];
    const uint32_t sb = smem_u32(smemc);

    const int nrows = S_;
    const int row0 = blockIdx.x * BM;
    if (row0 >= nrows) return;
    const int yoff = blockIdx.y * 112;

    const __half* ApH = (MODE == 3) ? g_Ph : g_Yh;
    const __half* Wh  = (MODE == 3) ? g_W3h : g_W4h;

    const int t = threadIdx.x, lane = t & 31, wid = t >> 5;
    const int warpM = wid & 3, warpN = wid >> 2;
    const int grp = lane >> 2, qid = lane & 3;
    const int r8 = lane & 7, sub = lane >> 3;

    const uint32_t bB = (uint32_t)(ATILEB + (warpN * 56 + (sub >> 1) * 8 + r8) * 144
                                   + (sub & 1) * 16);
    const uint32_t bB6 = (uint32_t)(ATILEB + (warpN * 56 + 48 + r8) * 144
                                    + (sub & 1) * 16);
    const uint32_t aB = (uint32_t)((warpM * 32 + (sub & 1) * 8 + r8) * 144
                                   + (sub >> 1) * 16);

    const __half* asrc[4]; bool avalid[4];
#pragma unroll
    for (int i = 0; i < 4; i++) {
        int idx = i * 256 + t;
        int m = idx >> 3, g = idx & 7;
        int grow = row0 + m;
        avalid[i] = grow < nrows;
        asrc[i] = ApH + (size_t)(avalid[i] ? grow : 0) * ASTH + g * 8;
    }

    auto issue = [&](int kt) {
        const uint32_t sbase = sb + (uint32_t)(kt & 1) * STAGEB;
        const int kb = kt * BK;
#pragma unroll
        for (int i = 0; i < 4; i++) {
            int idx = i * 256 + t;
            int m = idx >> 3, g = idx & 7;
            uint32_t sz = (avalid[i] && (kb + g * 8 + 8) <= KLIM) ? 16u : 0u;
            cp16(sbase + (uint32_t)(m * 144 + g * 16), asrc[i] + kb, sz);
        }
#pragma unroll
        for (int i = 0; i < 4; i++) {
            int idx = i * 256 + t;
            if (idx < 896) {
                int n = idx >> 3, g = idx & 7;
                int gcol = yoff + n;
                bool v = gcol < NW;
                uint32_t sz = (v && (kb + g * 8 + 8) <= KLIM) ? 16u : 0u;
                cp16(sbase + (uint32_t)(ATILEB + n * 144 + g * 16),
                     Wh + (size_t)(v ? gcol : 0) * WST + g * 8 + kb, sz);
            }
        }
        CP_COMMIT();
    };

    float acc[2][7][4];
#pragma unroll
    for (int mt = 0; mt < 2; mt++)
#pragma unroll
        for (int nt = 0; nt < 7; nt++)
#pragma unroll
            for (int c = 0; c < 4; c++) acc[mt][nt][c] = 0.0f;

    issue(0);
    for (int kt = 0; kt < KT; kt++) {
        CP_WAIT(0);
        __syncthreads();
        if (kt + 1 < KT) issue(kt + 1);

        const uint32_t stb = sb + (uint32_t)(kt & 1) * STAGEB;
#pragma unroll
        for (int s16 = 0; s16 < 4; s16++) {
            const uint32_t ks = (uint32_t)(s16 * 32);
            uint32_t bf[7][2];
            ldsm4(bf[0][0], bf[0][1], bf[1][0], bf[1][1], stb + bB + ks);
            ldsm4(bf[2][0], bf[2][1], bf[3][0], bf[3][1], stb + bB + 2304 + ks);
            ldsm4(bf[4][0], bf[4][1], bf[5][0], bf[5][1], stb + bB + 4608 + ks);
            ldsm2(bf[6][0], bf[6][1], stb + bB6 + ks);
#pragma unroll
            for (int mt = 0; mt < 2; mt++) {
                uint32_t a0, a1, a2, a3;
                ldsm4(a0, a1, a2, a3, stb + aB + (uint32_t)(mt * 2304) + ks);
#pragma unroll
                for (int nt = 0; nt < 7; nt++)
                    mma_f16(acc[mt][nt][0], acc[mt][nt][1],
                            acc[mt][nt][2], acc[mt][nt][3],
                            a0, a1, a2, a3, bf[nt][0], bf[nt][1]);
            }
        }
        __syncthreads();
    }

    float sc0[2], sc1[2];
#pragma unroll
    for (int mt = 0; mt < 2; mt++) {
        int r = row0 + warpM * 32 + mt * 16 + grp;
        sc0[mt] = (MODE == 3 && r < S_) ? g_invN[r] : 1.0f;
        sc1[mt] = (MODE == 3 && r + 8 < S_) ? g_invN[r + 8] : 1.0f;
    }

#pragma unroll
    for (int mt = 0; mt < 2; mt++) {
        int r = row0 + warpM * 32 + mt * 16 + grp;
#pragma unroll
        for (int nt = 0; nt < 7; nt++) {
            int gcol = yoff + warpN * 56 + nt * 8 + 2 * qid;
            if (gcol >= NW) continue;
            float b0 = bias[gcol];
            float b1 = bias[gcol + 1];
            float v0 = fmaxf(acc[mt][nt][0] * sc0[mt] + b0, 0.0f);
            float v1 = fmaxf(acc[mt][nt][1] * sc0[mt] + b1, 0.0f);
            float v2 = fmaxf(acc[mt][nt][2] * sc1[mt] + b0, 0.0f);
            float v3 = fmaxf(acc[mt][nt][3] * sc1[mt] + b1, 0.0f);
            if (MODE == 4) {
                if (r < nrows)
                    *(float2*)(OutExt + (size_t)r * D_ + gcol) = make_float2(v0, v1);
                if (r + 8 < nrows)
                    *(float2*)(OutExt + (size_t)(r + 8) * D_ + gcol) = make_float2(v2, v3);
            } else {
                if (r < nrows)
                    *(uint32_t*)(g_Yh + (size_t)r * H_ + gcol) = packh2(v0, v1);
                if (r + 8 < nrows)
                    *(uint32_t*)(g_Yh + (size_t)(r + 8) * H_ + gcol) = packh2(v2, v3);
            }
        }
    }
}

// ---------------------------------------------------------------------------------
extern "C" void kernel_launch(void* const* d_in, const int* in_sizes, int n_in,
                              void* d_out, int out_size) {
    (void)in_sizes; (void)n_in; (void)out_size;
    const float* all_x     = (const float*)d_in[0];
    const int*   numInputs = (const int*)  d_in[1];
    const float* W1 = (const float*)d_in[2];
    const float* b1 = (const float*)d_in[3];
    const float* W2 = (const float*)d_in[4];
    const float* b2 = (const float*)d_in[5];
    const float* W3 = (const float*)d_in[6];
    const float* b3 = (const float*)d_in[7];
    const float* W4 = (const float*)d_in[8];
    const float* b4 = (const float*)d_in[9];
    float* out = (float*)d_out;

    const int SMEM_F1 = 128 * 848 + 3 * 112 * 144;               // 156928 (fused mode 1)
    const int SMEM_F2 = SMEM_F1 + 128 * 116 * 4 + 390 * 4;       // +ep+segs = 217880
    const int SMEM_S  = 2 * (128 * 144 + 112 * 144);             // 69120 (modes 3,4)
    cudaFuncSetAttribute(gemm_fused<1>, cudaFuncAttributeMaxDynamicSharedMemorySize, SMEM_F1);
    cudaFuncSetAttribute(gemm_fused<2>, cudaFuncAttributeMaxDynamicSharedMemorySize, SMEM_F2);
    cudaFuncSetAttribute(gemm_h<3, D_>, cudaFuncAttributeMaxDynamicSharedMemorySize, SMEM_S);
    cudaFuncSetAttribute(gemm_h<4, H_>, cudaFuncAttributeMaxDynamicSharedMemorySize, SMEM_S);

    setup_kernel<<<1, 256>>>(numInputs);
    {
        int total = S_ * D_ / 4 + 2 * (D_ * 53) + H_ * 53 + D_ * (H_ / 8) + S_ * M_;
        prep_kernel<<<(total + 255) / 256, 256>>>(W1, W2, W3, W4);
    }
    convert_x_kernel<<<(S_ * M_ * 53 + 255) / 256, 256>>>(all_x);

    // layer 1: H1 = relu(Xh @ W1^T + b1)  (A-resident, all 420 cols per CTA)
    gemm_fused<1><<<(S_ * M_ + 127) / 128, 256, SMEM_F1>>>(b1);
    // layer 2 + ragged sum-pool into g_pooled
    gemm_fused<2><<<(S_ * M_ + 127) / 128, 256, SMEM_F2>>>(b2);
    // pooled -> fp16
    convert_p_kernel<<<(S_ * 53 + 255) / 256, 256>>>();
    // layer 3: Y = relu((Ph @ W3^T)/n + b3)   [S, 840] -> fp16
    gemm_h<3, D_><<<dim3(S_ / 128, 8), 256, SMEM_S>>>(b3, nullptr);
    // layer 4: out = relu(Y @ W4^T + b4)      [S, 420]
    gemm_h<4, H_><<<dim3(S_ / 128, 4), 256, SMEM_S>>>(b4, out);
}